// round 6
// baseline (speedup 1.0000x reference)
#include <cuda_runtime.h>
#include <cuda_bf16.h>
#include <cstdint>

#define N_NODES   50000
#define N_EDGES   800000
#define D_FEAT    128
#define HIDDEN    256
#define N_PAD     50048          // 391 * 128
#define M_TILES   391

// ---------------- scratch (static device globals) ---------------------------
__device__ int   g_deg[N_NODES];
__device__ int   g_rowptr[N_NODES + 1];
__device__ int   g_cursor[N_NODES];
__device__ float g_invdeg[N_NODES];
__device__ int   g_nbr[N_EDGES];
__device__ __nv_bfloat16 g_Ahi[(size_t)N_PAD * 256];   // [mean|x] hi; pad rows stay 0
__device__ __nv_bfloat16 g_Alo[(size_t)N_PAD * 256];
__device__ __nv_bfloat16 g_Bhi[256 * 256];             // B^T: [n][k], k-major
__device__ __nv_bfloat16 g_Blo[256 * 256];
__device__ float g_p[N_NODES * 2];   // h @ W2l (atomic-accumulated)
__device__ float g_q[N_NODES * 2];   // h @ W2r

// ---------------- CSR build --------------------------------------------------
__global__ void k_zero() {
    int i = blockIdx.x * blockDim.x + threadIdx.x;
    if (i < N_NODES) g_deg[i] = 0;
    if (i < N_NODES * 2) { g_p[i] = 0.f; g_q[i] = 0.f; }
}
__global__ void k_hist(const int* __restrict__ dst) {
    int e = blockIdx.x * blockDim.x + threadIdx.x;
    if (e < N_EDGES) atomicAdd(&g_deg[dst[e]], 1);
}

// 1 block, 1024 threads, thread-coarsened single-pass scan (CH=49 elems/thread)
__global__ void k_scan() {
    const int CH = 49;                 // 1024*49 = 50176 >= N_NODES
    __shared__ int warp_tot[32];
    int tid = threadIdx.x, lane = tid & 31, wid = tid >> 5;
    int start = tid * CH;
    int s = 0;
#pragma unroll 7
    for (int i = 0; i < CH; i++) {
        int idx = start + i;
        if (idx < N_NODES) s += g_deg[idx];
    }
    int xv = s;
#pragma unroll
    for (int o = 1; o < 32; o <<= 1) {
        int t = __shfl_up_sync(0xffffffffu, xv, o);
        if (lane >= o) xv += t;
    }
    if (lane == 31) warp_tot[wid] = xv;
    __syncthreads();
    if (wid == 0) {
        int w = warp_tot[lane];
#pragma unroll
        for (int o = 1; o < 32; o <<= 1) {
            int t = __shfl_up_sync(0xffffffffu, w, o);
            if (lane >= o) w += t;
        }
        warp_tot[lane] = w;
    }
    __syncthreads();
    int prefix = xv - s + ((wid > 0) ? warp_tot[wid - 1] : 0);
    int run = prefix;
#pragma unroll 7
    for (int i = 0; i < CH; i++) {
        int idx = start + i;
        if (idx < N_NODES) {
            int v = g_deg[idx];
            g_rowptr[idx] = run;
            g_cursor[idx] = run;
            g_invdeg[idx] = 1.0f / (float)(v > 0 ? v : 1);
            run += v;
        }
    }
    if (tid == 1023) g_rowptr[N_NODES] = run;
}
__global__ void k_scatter(const int* __restrict__ src, const int* __restrict__ dst) {
    int e = blockIdx.x * blockDim.x + threadIdx.x;
    if (e < N_EDGES) {
        int d = dst[e];
        int pos = atomicAdd(&g_cursor[d], 1);
        g_nbr[pos] = src[e];
    }
}

// ---------------- bf16 split helpers ----------------------------------------
__device__ __forceinline__ void split_bf16(float v, unsigned short& h, unsigned short& l) {
    __nv_bfloat16 bh = __float2bfloat16_rn(v);
    float r = v - __bfloat162float(bh);
    __nv_bfloat16 bl = __float2bfloat16_rn(r);
    h = __bfloat16_as_ushort(bh);
    l = __bfloat16_as_ushort(bl);
}

// agg layer1 (warp/node) + convert mean to bf16 hi/lo into A cols [0,128)
__global__ void k_agg1c(const float* __restrict__ x) {
    int warp = (blockIdx.x * blockDim.x + threadIdx.x) >> 5;
    int lane = threadIdx.x & 31;
    if (warp >= N_NODES) return;
    int beg = g_rowptr[warp], end = g_rowptr[warp + 1];
    float4 acc = make_float4(0.f, 0.f, 0.f, 0.f);
    for (int j = beg; j < end; j++) {
        int s = g_nbr[j];
        float4 v = *(const float4*)(x + (size_t)s * D_FEAT + lane * 4);
        acc.x += v.x; acc.y += v.y; acc.z += v.z; acc.w += v.w;
    }
    float id = g_invdeg[warp];
    acc.x *= id; acc.y *= id; acc.z *= id; acc.w *= id;
    unsigned short h0, h1, h2, h3, l0, l1, l2, l3;
    split_bf16(acc.x, h0, l0); split_bf16(acc.y, h1, l1);
    split_bf16(acc.z, h2, l2); split_bf16(acc.w, h3, l3);
    uint2 ph, pl;
    ph.x = (uint32_t)h0 | ((uint32_t)h1 << 16);
    ph.y = (uint32_t)h2 | ((uint32_t)h3 << 16);
    pl.x = (uint32_t)l0 | ((uint32_t)l1 << 16);
    pl.y = (uint32_t)l2 | ((uint32_t)l3 << 16);
    size_t off = (size_t)warp * 256 + lane * 4;
    *reinterpret_cast<uint2*>(&g_Ahi[off]) = ph;
    *reinterpret_cast<uint2*>(&g_Alo[off]) = pl;
}

// convert x into A cols [128,256)
__global__ void k_convx(const float* __restrict__ x) {
    int i = blockIdx.x * blockDim.x + threadIdx.x;
    if (i >= N_NODES * 32) return;
    int node = i >> 5, lane = i & 31;
    float4 v = *(const float4*)(x + (size_t)node * D_FEAT + lane * 4);
    unsigned short h0, h1, h2, h3, l0, l1, l2, l3;
    split_bf16(v.x, h0, l0); split_bf16(v.y, h1, l1);
    split_bf16(v.z, h2, l2); split_bf16(v.w, h3, l3);
    uint2 ph, pl;
    ph.x = (uint32_t)h0 | ((uint32_t)h1 << 16);
    ph.y = (uint32_t)h2 | ((uint32_t)h3 << 16);
    pl.x = (uint32_t)l0 | ((uint32_t)l1 << 16);
    pl.y = (uint32_t)l2 | ((uint32_t)l3 << 16);
    size_t off = (size_t)node * 256 + 128 + lane * 4;
    *reinterpret_cast<uint2*>(&g_Ahi[off]) = ph;
    *reinterpret_cast<uint2*>(&g_Alo[off]) = pl;
}

// B^T build: g_B[n][k] = W1[k][n], W1 = [W1l ; W1r]
__global__ void k_convW(const float* __restrict__ W1l, const float* __restrict__ W1r) {
    int i = blockIdx.x * blockDim.x + threadIdx.x;
    if (i >= 256 * 256) return;
    int k = i >> 8, n = i & 255;
    float v = (k < 128) ? W1l[k * 256 + n] : W1r[(k - 128) * 256 + n];
    unsigned short h, l;
    split_bf16(v, h, l);
    g_Bhi[n * 256 + k] = __ushort_as_bfloat16(h);
    g_Blo[n * 256 + k] = __ushort_as_bfloat16(l);
}

// ---------------- HMMA GEMM1 + fused layer-2 projections ---------------------
// (R4 proven version) block tile 128x128, 8 warps = 4(M) x 2(N), warp tile 32x64
// K loop: 4 chunks of 64. smem stride: 72 halves (144B) per row.
#define SA_HI   0
#define SA_LO   18432
#define SB_HI   36864
#define SB_LO   55296
#define SBIAS   73728     // 128 f32
#define SW2L    74240     // 128 float2
#define SW2R    75264     // 128 float2
#define SM_TOT  76288

__device__ __forceinline__ void mma_bf16(float* d, const uint32_t* a,
                                         uint32_t b0, uint32_t b1) {
    asm volatile(
        "mma.sync.aligned.m16n8k16.row.col.f32.bf16.bf16.f32 "
        "{%0,%1,%2,%3}, {%4,%5,%6,%7}, {%8,%9}, {%0,%1,%2,%3};"
        : "+f"(d[0]), "+f"(d[1]), "+f"(d[2]), "+f"(d[3])
        : "r"(a[0]), "r"(a[1]), "r"(a[2]), "r"(a[3]), "r"(b0), "r"(b1));
}

__global__ void __launch_bounds__(256, 1)
k_gemm1_mma(const float* __restrict__ b1,
            const float* __restrict__ W2l, const float* __restrict__ W2r,
            float* __restrict__ h) {
    extern __shared__ char smem[];
    int tid  = threadIdx.x, lane = tid & 31, warp = tid >> 5;
    int warpM = warp & 3, warpN = warp >> 2;
    int m0 = blockIdx.x * 128, n0 = blockIdx.y * 128;

    float*  bias = (float*)(smem + SBIAS);
    float2* w2l  = (float2*)(smem + SW2L);
    float2* w2r  = (float2*)(smem + SW2R);
    if (tid < 128) {
        bias[tid] = b1[n0 + tid];
        w2l[tid]  = ((const float2*)W2l)[n0 + tid];
        w2r[tid]  = ((const float2*)W2r)[n0 + tid];
    }

    float acc[2][8][4];
#pragma unroll
    for (int mt = 0; mt < 2; mt++)
#pragma unroll
        for (int nt = 0; nt < 8; nt++)
#pragma unroll
            for (int j = 0; j < 4; j++) acc[mt][nt][j] = 0.f;

#pragma unroll 1
    for (int c = 0; c < 4; c++) {
        __syncthreads();
#pragma unroll
        for (int t = 0; t < 4; t++) {
            int idx = tid + t * 256;
            int r = idx >> 3, q = idx & 7;
            size_t ga = (size_t)(m0 + r) * 256 + c * 64 + q * 8;
            size_t gb = (size_t)(n0 + r) * 256 + c * 64 + q * 8;
            uint32_t so = (uint32_t)(r * 144 + q * 16);
            *(uint4*)(smem + SA_HI + so) = *(const uint4*)(g_Ahi + ga);
            *(uint4*)(smem + SA_LO + so) = *(const uint4*)(g_Alo + ga);
            *(uint4*)(smem + SB_HI + so) = *(const uint4*)(g_Bhi + gb);
            *(uint4*)(smem + SB_LO + so) = *(const uint4*)(g_Blo + gb);
        }
        __syncthreads();
#pragma unroll
        for (int s = 0; s < 4; s++) {
            int kb = s * 16 + (lane & 3) * 2;       // lane's first k element
            int ar = warpM * 32 + (lane >> 2);
            uint32_t ah[2][4], al[2][4];
#pragma unroll
            for (int mt = 0; mt < 2; mt++) {
                int r0 = ar + mt * 16;
                uint32_t o00 = (uint32_t)(r0 * 144 + kb * 2);
                uint32_t o10 = o00 + 8 * 144;
                ah[mt][0] = *(const uint32_t*)(smem + SA_HI + o00);
                ah[mt][1] = *(const uint32_t*)(smem + SA_HI + o10);
                ah[mt][2] = *(const uint32_t*)(smem + SA_HI + o00 + 16);
                ah[mt][3] = *(const uint32_t*)(smem + SA_HI + o10 + 16);
                al[mt][0] = *(const uint32_t*)(smem + SA_LO + o00);
                al[mt][1] = *(const uint32_t*)(smem + SA_LO + o10);
                al[mt][2] = *(const uint32_t*)(smem + SA_LO + o00 + 16);
                al[mt][3] = *(const uint32_t*)(smem + SA_LO + o10 + 16);
            }
#pragma unroll
            for (int nt = 0; nt < 8; nt++) {
                int bn = warpN * 64 + nt * 8 + (lane >> 2);
                uint32_t bo = (uint32_t)(bn * 144 + kb * 2);
                uint32_t bh0 = *(const uint32_t*)(smem + SB_HI + bo);
                uint32_t bh1 = *(const uint32_t*)(smem + SB_HI + bo + 16);
                uint32_t bl0 = *(const uint32_t*)(smem + SB_LO + bo);
                uint32_t bl1 = *(const uint32_t*)(smem + SB_LO + bo + 16);
#pragma unroll
                for (int mt = 0; mt < 2; mt++) {
                    mma_bf16(acc[mt][nt], ah[mt], bh0, bh1);
                    mma_bf16(acc[mt][nt], ah[mt], bl0, bl1);
                    mma_bf16(acc[mt][nt], al[mt], bh0, bh1);
                }
            }
        }
    }

    // epilogue: bias + relu + store h; fused projections p = h@W2l, q = h@W2r
#pragma unroll
    for (int mt = 0; mt < 2; mt++) {
        int rowA = m0 + warpM * 32 + mt * 16 + (lane >> 2);
        int rowB = rowA + 8;
        float pla0 = 0.f, pla1 = 0.f, pra0 = 0.f, pra1 = 0.f;
        float plb0 = 0.f, plb1 = 0.f, prb0 = 0.f, prb1 = 0.f;
#pragma unroll
        for (int nt = 0; nt < 8; nt++) {
            int cl = warpN * 64 + nt * 8 + (lane & 3) * 2;  // local col 0..127
            float bz0 = bias[cl], bz1 = bias[cl + 1];
            float h0 = fmaxf(acc[mt][nt][0] + bz0, 0.f);
            float h1 = fmaxf(acc[mt][nt][1] + bz1, 0.f);
            float h2 = fmaxf(acc[mt][nt][2] + bz0, 0.f);
            float h3 = fmaxf(acc[mt][nt][3] + bz1, 0.f);
            if (rowA < N_NODES)
                *(float2*)(h + (size_t)rowA * 256 + n0 + cl) = make_float2(h0, h1);
            if (rowB < N_NODES)
                *(float2*)(h + (size_t)rowB * 256 + n0 + cl) = make_float2(h2, h3);
            float2 wl0 = w2l[cl], wl1 = w2l[cl + 1];
            float2 wr0 = w2r[cl], wr1 = w2r[cl + 1];
            pla0 += h0 * wl0.x + h1 * wl1.x;  pla1 += h0 * wl0.y + h1 * wl1.y;
            pra0 += h0 * wr0.x + h1 * wr1.x;  pra1 += h0 * wr0.y + h1 * wr1.y;
            plb0 += h2 * wl0.x + h3 * wl1.x;  plb1 += h2 * wl0.y + h3 * wl1.y;
            prb0 += h2 * wr0.x + h3 * wr1.x;  prb1 += h2 * wr0.y + h3 * wr1.y;
        }
#pragma unroll
        for (int o = 1; o <= 2; o <<= 1) {
            pla0 += __shfl_xor_sync(0xffffffffu, pla0, o);
            pla1 += __shfl_xor_sync(0xffffffffu, pla1, o);
            pra0 += __shfl_xor_sync(0xffffffffu, pra0, o);
            pra1 += __shfl_xor_sync(0xffffffffu, pra1, o);
            plb0 += __shfl_xor_sync(0xffffffffu, plb0, o);
            plb1 += __shfl_xor_sync(0xffffffffu, plb1, o);
            prb0 += __shfl_xor_sync(0xffffffffu, prb0, o);
            prb1 += __shfl_xor_sync(0xffffffffu, prb1, o);
        }
        if ((lane & 3) == 0) {
            if (rowA < N_NODES) {
                atomicAdd(&g_p[rowA * 2 + 0], pla0);
                atomicAdd(&g_p[rowA * 2 + 1], pla1);
                atomicAdd(&g_q[rowA * 2 + 0], pra0);
                atomicAdd(&g_q[rowA * 2 + 1], pra1);
            }
            if (rowB < N_NODES) {
                atomicAdd(&g_p[rowB * 2 + 0], plb0);
                atomicAdd(&g_p[rowB * 2 + 1], plb1);
                atomicAdd(&g_q[rowB * 2 + 0], prb0);
                atomicAdd(&g_q[rowB * 2 + 1], prb1);
            }
        }
    }
}

// ---------------- layer-2: aggregate p, add q, sigmoid, store ----------------
__global__ void k_aggout(const float* __restrict__ b2, float* __restrict__ out) {
    int i = blockIdx.x * blockDim.x + threadIdx.x;
    if (i >= N_NODES) return;
    int beg = g_rowptr[i], end = g_rowptr[i + 1];
    float a0 = 0.f, a1 = 0.f;
    const float2* p2 = (const float2*)g_p;
    for (int j = beg; j < end; j++) {
        float2 v = p2[g_nbr[j]];
        a0 += v.x; a1 += v.y;
    }
    float id = g_invdeg[i];
    float v0 = a0 * id + g_q[i * 2 + 0] + b2[0];
    float v1 = a1 * id + g_q[i * 2 + 1] + b2[1];
    out[i * 2 + 0] = 1.0f / (1.0f + __expf(-v0));
    out[i * 2 + 1] = 1.0f / (1.0f + __expf(-v1));
}

// ---------------- launch ------------------------------------------------------
extern "C" void kernel_launch(void* const* d_in, const int* in_sizes, int n_in,
                              void* d_out, int out_size) {
    const float* x   = (const float*)d_in[0];
    const int*   ei  = (const int*)d_in[1];
    const float* W1l = (const float*)d_in[2];
    const float* W1r = (const float*)d_in[3];
    const float* b1  = (const float*)d_in[4];
    const float* W2l = (const float*)d_in[5];
    const float* W2r = (const float*)d_in[6];
    const float* b2  = (const float*)d_in[7];

    float* out = (float*)d_out;
    float* emb = out + (size_t)N_NODES * 2;

    const int* src = ei;
    const int* dst = ei + N_EDGES;

    cudaFuncSetAttribute(k_gemm1_mma, cudaFuncAttributeMaxDynamicSharedMemorySize, SM_TOT);

    // conversions + zeroing (independent of CSR)
    k_convW<<<(256 * 256 + 255) / 256, 256>>>(W1l, W1r);
    k_convx<<<(N_NODES * 32 + 255) / 256, 256>>>(x);
    k_zero<<<(N_NODES * 2 + 255) / 256, 256>>>();

    // CSR build
    k_hist<<<(N_EDGES + 255) / 256, 256>>>(dst);
    k_scan<<<1, 1024>>>();
    k_scatter<<<(N_EDGES + 255) / 256, 256>>>(src, dst);

    // layer 1 aggregation + A conversion
    k_agg1c<<<(N_NODES + 7) / 8, 256>>>(x);

    // layer-1 GEMM (HMMA) + fused layer-2 projections
    dim3 g1(M_TILES, 2);
    k_gemm1_mma<<<g1, 256, SM_TOT>>>(b1, W2l, W2r, emb);

    // layer-2: aggregate 2-dim projections + output
    k_aggout<<<(N_NODES + 255) / 256, 256>>>(b2, out);
}

// round 7
// speedup vs baseline: 1.3518x; 1.3518x over previous
#include <cuda_runtime.h>
#include <cuda_bf16.h>
#include <cstdint>

#define N_NODES   50000
#define N_EDGES   800000
#define D_FEAT    128
#define HIDDEN    256
#define N_PAD     50048          // 391 * 128
#define M_TILES   391

// ---------------- scratch (static device globals) ---------------------------
__device__ int   g_deg[N_NODES];
__device__ int   g_rowptr[N_NODES + 1];
__device__ int   g_cursor[N_NODES];
__device__ float g_invdeg[N_NODES];
__device__ int   g_nbr[N_EDGES];
__device__ __nv_bfloat16 g_Ahi[(size_t)N_PAD * 256];   // [mean|x] hi; pad rows stay 0
__device__ __nv_bfloat16 g_Alo[(size_t)N_PAD * 256];
__device__ __nv_bfloat16 g_Bhi[256 * 256];             // B^T: [n][k], k-major
__device__ __nv_bfloat16 g_Blo[256 * 256];
__device__ float g_p[N_NODES * 2];   // h @ W2l (atomic-accumulated)
__device__ float g_q[N_NODES * 2];   // h @ W2r

// ---------------- CSR build --------------------------------------------------
__global__ void k_zero() {
    int i = blockIdx.x * blockDim.x + threadIdx.x;
    if (i < N_NODES) g_deg[i] = 0;
    if (i < N_NODES * 2) { g_p[i] = 0.f; g_q[i] = 0.f; }
}
__global__ void k_hist(const int* __restrict__ dst) {
    int e = blockIdx.x * blockDim.x + threadIdx.x;
    if (e < N_EDGES) atomicAdd(&g_deg[dst[e]], 1);
}

// 1 block, 1024 threads = 32 warps. Warp w owns contiguous [w*1568, w*1568+1568).
// All accesses lane-strided (coalesced). 49 warp-scan rounds, 2 block syncs total.
__global__ void k_scan() {
    const int ROUNDS = 49;              // 49*32 = 1568 elems per warp; 32*1568 = 50176
    __shared__ int warp_tot[32];
    int tid = threadIdx.x, lane = tid & 31, wid = tid >> 5;
    int base = wid * (ROUNDS * 32);

    // pass 1: warp total (coalesced)
    int s = 0;
#pragma unroll 7
    for (int j = 0; j < ROUNDS; j++) {
        int idx = base + j * 32 + lane;
        if (idx < N_NODES) s += g_deg[idx];
    }
#pragma unroll
    for (int o = 16; o > 0; o >>= 1) s += __shfl_xor_sync(0xffffffffu, s, o);
    if (lane == 0) warp_tot[wid] = s;
    __syncthreads();
    if (wid == 0) {
        int w = warp_tot[lane];
        int xw = w;
#pragma unroll
        for (int o = 1; o < 32; o <<= 1) {
            int t = __shfl_up_sync(0xffffffffu, xw, o);
            if (lane >= o) xw += t;
        }
        warp_tot[lane] = xw;            // inclusive over warp totals
    }
    __syncthreads();
    int carry = (wid > 0) ? warp_tot[wid - 1] : 0;

    // pass 2: 49 coalesced warp-exclusive-scan rounds with running carry
#pragma unroll 7
    for (int j = 0; j < ROUNDS; j++) {
        int idx = base + j * 32 + lane;
        int v = (idx < N_NODES) ? g_deg[idx] : 0;
        int xv = v;
#pragma unroll
        for (int o = 1; o < 32; o <<= 1) {
            int t = __shfl_up_sync(0xffffffffu, xv, o);
            if (lane >= o) xv += t;
        }
        int excl = carry + xv - v;
        if (idx < N_NODES) {
            g_rowptr[idx] = excl;
            g_cursor[idx] = excl;
            g_invdeg[idx] = 1.0f / (float)(v > 0 ? v : 1);
        }
        carry += __shfl_sync(0xffffffffu, xv, 31);
    }
    if (wid == 31 && lane == 31) g_rowptr[N_NODES] = carry;
}
__global__ void k_scatter(const int* __restrict__ src, const int* __restrict__ dst) {
    int e = blockIdx.x * blockDim.x + threadIdx.x;
    if (e < N_EDGES) {
        int d = dst[e];
        int pos = atomicAdd(&g_cursor[d], 1);
        g_nbr[pos] = src[e];
    }
}

// ---------------- bf16 split helpers ----------------------------------------
__device__ __forceinline__ void split_bf16(float v, unsigned short& h, unsigned short& l) {
    __nv_bfloat16 bh = __float2bfloat16_rn(v);
    float r = v - __bfloat162float(bh);
    __nv_bfloat16 bl = __float2bfloat16_rn(r);
    h = __bfloat16_as_ushort(bh);
    l = __bfloat16_as_ushort(bl);
}

// agg layer1 (warp/node) + convert mean to bf16 hi/lo into A cols [0,128)
__global__ void k_agg1c(const float* __restrict__ x) {
    int warp = (blockIdx.x * blockDim.x + threadIdx.x) >> 5;
    int lane = threadIdx.x & 31;
    if (warp >= N_NODES) return;
    int beg = g_rowptr[warp], end = g_rowptr[warp + 1];
    float4 acc = make_float4(0.f, 0.f, 0.f, 0.f);
    for (int j = beg; j < end; j++) {
        int s = g_nbr[j];
        float4 v = *(const float4*)(x + (size_t)s * D_FEAT + lane * 4);
        acc.x += v.x; acc.y += v.y; acc.z += v.z; acc.w += v.w;
    }
    float id = g_invdeg[warp];
    acc.x *= id; acc.y *= id; acc.z *= id; acc.w *= id;
    unsigned short h0, h1, h2, h3, l0, l1, l2, l3;
    split_bf16(acc.x, h0, l0); split_bf16(acc.y, h1, l1);
    split_bf16(acc.z, h2, l2); split_bf16(acc.w, h3, l3);
    uint2 ph, pl;
    ph.x = (uint32_t)h0 | ((uint32_t)h1 << 16);
    ph.y = (uint32_t)h2 | ((uint32_t)h3 << 16);
    pl.x = (uint32_t)l0 | ((uint32_t)l1 << 16);
    pl.y = (uint32_t)l2 | ((uint32_t)l3 << 16);
    size_t off = (size_t)warp * 256 + lane * 4;
    *reinterpret_cast<uint2*>(&g_Ahi[off]) = ph;
    *reinterpret_cast<uint2*>(&g_Alo[off]) = pl;
}

// convert x into A cols [128,256)
__global__ void k_convx(const float* __restrict__ x) {
    int i = blockIdx.x * blockDim.x + threadIdx.x;
    if (i >= N_NODES * 32) return;
    int node = i >> 5, lane = i & 31;
    float4 v = *(const float4*)(x + (size_t)node * D_FEAT + lane * 4);
    unsigned short h0, h1, h2, h3, l0, l1, l2, l3;
    split_bf16(v.x, h0, l0); split_bf16(v.y, h1, l1);
    split_bf16(v.z, h2, l2); split_bf16(v.w, h3, l3);
    uint2 ph, pl;
    ph.x = (uint32_t)h0 | ((uint32_t)h1 << 16);
    ph.y = (uint32_t)h2 | ((uint32_t)h3 << 16);
    pl.x = (uint32_t)l0 | ((uint32_t)l1 << 16);
    pl.y = (uint32_t)l2 | ((uint32_t)l3 << 16);
    size_t off = (size_t)node * 256 + 128 + lane * 4;
    *reinterpret_cast<uint2*>(&g_Ahi[off]) = ph;
    *reinterpret_cast<uint2*>(&g_Alo[off]) = pl;
}

// B^T build: g_B[n][k] = W1[k][n], W1 = [W1l ; W1r]
__global__ void k_convW(const float* __restrict__ W1l, const float* __restrict__ W1r) {
    int i = blockIdx.x * blockDim.x + threadIdx.x;
    if (i >= 256 * 256) return;
    int k = i >> 8, n = i & 255;
    float v = (k < 128) ? W1l[k * 256 + n] : W1r[(k - 128) * 256 + n];
    unsigned short h, l;
    split_bf16(v, h, l);
    g_Bhi[n * 256 + k] = __ushort_as_bfloat16(h);
    g_Blo[n * 256 + k] = __ushort_as_bfloat16(l);
}

// ---------------- HMMA GEMM1 + fused layer-2 projections ---------------------
// (R4 proven version) block tile 128x128, 8 warps = 4(M) x 2(N), warp tile 32x64
// K loop: 4 chunks of 64. smem stride: 72 halves (144B) per row.
#define SA_HI   0
#define SA_LO   18432
#define SB_HI   36864
#define SB_LO   55296
#define SBIAS   73728     // 128 f32
#define SW2L    74240     // 128 float2
#define SW2R    75264     // 128 float2
#define SM_TOT  76288

__device__ __forceinline__ void mma_bf16(float* d, const uint32_t* a,
                                         uint32_t b0, uint32_t b1) {
    asm volatile(
        "mma.sync.aligned.m16n8k16.row.col.f32.bf16.bf16.f32 "
        "{%0,%1,%2,%3}, {%4,%5,%6,%7}, {%8,%9}, {%0,%1,%2,%3};"
        : "+f"(d[0]), "+f"(d[1]), "+f"(d[2]), "+f"(d[3])
        : "r"(a[0]), "r"(a[1]), "r"(a[2]), "r"(a[3]), "r"(b0), "r"(b1));
}

__global__ void __launch_bounds__(256, 1)
k_gemm1_mma(const float* __restrict__ b1,
            const float* __restrict__ W2l, const float* __restrict__ W2r,
            float* __restrict__ h) {
    extern __shared__ char smem[];
    int tid  = threadIdx.x, lane = tid & 31, warp = tid >> 5;
    int warpM = warp & 3, warpN = warp >> 2;
    int m0 = blockIdx.x * 128, n0 = blockIdx.y * 128;

    float*  bias = (float*)(smem + SBIAS);
    float2* w2l  = (float2*)(smem + SW2L);
    float2* w2r  = (float2*)(smem + SW2R);
    if (tid < 128) {
        bias[tid] = b1[n0 + tid];
        w2l[tid]  = ((const float2*)W2l)[n0 + tid];
        w2r[tid]  = ((const float2*)W2r)[n0 + tid];
    }

    float acc[2][8][4];
#pragma unroll
    for (int mt = 0; mt < 2; mt++)
#pragma unroll
        for (int nt = 0; nt < 8; nt++)
#pragma unroll
            for (int j = 0; j < 4; j++) acc[mt][nt][j] = 0.f;

#pragma unroll 1
    for (int c = 0; c < 4; c++) {
        __syncthreads();
#pragma unroll
        for (int t = 0; t < 4; t++) {
            int idx = tid + t * 256;
            int r = idx >> 3, q = idx & 7;
            size_t ga = (size_t)(m0 + r) * 256 + c * 64 + q * 8;
            size_t gb = (size_t)(n0 + r) * 256 + c * 64 + q * 8;
            uint32_t so = (uint32_t)(r * 144 + q * 16);
            *(uint4*)(smem + SA_HI + so) = *(const uint4*)(g_Ahi + ga);
            *(uint4*)(smem + SA_LO + so) = *(const uint4*)(g_Alo + ga);
            *(uint4*)(smem + SB_HI + so) = *(const uint4*)(g_Bhi + gb);
            *(uint4*)(smem + SB_LO + so) = *(const uint4*)(g_Blo + gb);
        }
        __syncthreads();
#pragma unroll
        for (int s = 0; s < 4; s++) {
            int kb = s * 16 + (lane & 3) * 2;       // lane's first k element
            int ar = warpM * 32 + (lane >> 2);
            uint32_t ah[2][4], al[2][4];
#pragma unroll
            for (int mt = 0; mt < 2; mt++) {
                int r0 = ar + mt * 16;
                uint32_t o00 = (uint32_t)(r0 * 144 + kb * 2);
                uint32_t o10 = o00 + 8 * 144;
                ah[mt][0] = *(const uint32_t*)(smem + SA_HI + o00);
                ah[mt][1] = *(const uint32_t*)(smem + SA_HI + o10);
                ah[mt][2] = *(const uint32_t*)(smem + SA_HI + o00 + 16);
                ah[mt][3] = *(const uint32_t*)(smem + SA_HI + o10 + 16);
                al[mt][0] = *(const uint32_t*)(smem + SA_LO + o00);
                al[mt][1] = *(const uint32_t*)(smem + SA_LO + o10);
                al[mt][2] = *(const uint32_t*)(smem + SA_LO + o00 + 16);
                al[mt][3] = *(const uint32_t*)(smem + SA_LO + o10 + 16);
            }
#pragma unroll
            for (int nt = 0; nt < 8; nt++) {
                int bn = warpN * 64 + nt * 8 + (lane >> 2);
                uint32_t bo = (uint32_t)(bn * 144 + kb * 2);
                uint32_t bh0 = *(const uint32_t*)(smem + SB_HI + bo);
                uint32_t bh1 = *(const uint32_t*)(smem + SB_HI + bo + 16);
                uint32_t bl0 = *(const uint32_t*)(smem + SB_LO + bo);
                uint32_t bl1 = *(const uint32_t*)(smem + SB_LO + bo + 16);
#pragma unroll
                for (int mt = 0; mt < 2; mt++) {
                    mma_bf16(acc[mt][nt], ah[mt], bh0, bh1);
                    mma_bf16(acc[mt][nt], ah[mt], bl0, bl1);
                    mma_bf16(acc[mt][nt], al[mt], bh0, bh1);
                }
            }
        }
    }

    // epilogue: bias + relu + store h; fused projections p = h@W2l, q = h@W2r
#pragma unroll
    for (int mt = 0; mt < 2; mt++) {
        int rowA = m0 + warpM * 32 + mt * 16 + (lane >> 2);
        int rowB = rowA + 8;
        float pla0 = 0.f, pla1 = 0.f, pra0 = 0.f, pra1 = 0.f;
        float plb0 = 0.f, plb1 = 0.f, prb0 = 0.f, prb1 = 0.f;
#pragma unroll
        for (int nt = 0; nt < 8; nt++) {
            int cl = warpN * 64 + nt * 8 + (lane & 3) * 2;  // local col 0..127
            float bz0 = bias[cl], bz1 = bias[cl + 1];
            float h0 = fmaxf(acc[mt][nt][0] + bz0, 0.f);
            float h1 = fmaxf(acc[mt][nt][1] + bz1, 0.f);
            float h2 = fmaxf(acc[mt][nt][2] + bz0, 0.f);
            float h3 = fmaxf(acc[mt][nt][3] + bz1, 0.f);
            if (rowA < N_NODES)
                *(float2*)(h + (size_t)rowA * 256 + n0 + cl) = make_float2(h0, h1);
            if (rowB < N_NODES)
                *(float2*)(h + (size_t)rowB * 256 + n0 + cl) = make_float2(h2, h3);
            float2 wl0 = w2l[cl], wl1 = w2l[cl + 1];
            float2 wr0 = w2r[cl], wr1 = w2r[cl + 1];
            pla0 += h0 * wl0.x + h1 * wl1.x;  pla1 += h0 * wl0.y + h1 * wl1.y;
            pra0 += h0 * wr0.x + h1 * wr1.x;  pra1 += h0 * wr0.y + h1 * wr1.y;
            plb0 += h2 * wl0.x + h3 * wl1.x;  plb1 += h2 * wl0.y + h3 * wl1.y;
            prb0 += h2 * wr0.x + h3 * wr1.x;  prb1 += h2 * wr0.y + h3 * wr1.y;
        }
#pragma unroll
        for (int o = 1; o <= 2; o <<= 1) {
            pla0 += __shfl_xor_sync(0xffffffffu, pla0, o);
            pla1 += __shfl_xor_sync(0xffffffffu, pla1, o);
            pra0 += __shfl_xor_sync(0xffffffffu, pra0, o);
            pra1 += __shfl_xor_sync(0xffffffffu, pra1, o);
            plb0 += __shfl_xor_sync(0xffffffffu, plb0, o);
            plb1 += __shfl_xor_sync(0xffffffffu, plb1, o);
            prb0 += __shfl_xor_sync(0xffffffffu, prb0, o);
            prb1 += __shfl_xor_sync(0xffffffffu, prb1, o);
        }
        if ((lane & 3) == 0) {
            if (rowA < N_NODES) {
                atomicAdd(&g_p[rowA * 2 + 0], pla0);
                atomicAdd(&g_p[rowA * 2 + 1], pla1);
                atomicAdd(&g_q[rowA * 2 + 0], pra0);
                atomicAdd(&g_q[rowA * 2 + 1], pra1);
            }
            if (rowB < N_NODES) {
                atomicAdd(&g_p[rowB * 2 + 0], plb0);
                atomicAdd(&g_p[rowB * 2 + 1], plb1);
                atomicAdd(&g_q[rowB * 2 + 0], prb0);
                atomicAdd(&g_q[rowB * 2 + 1], prb1);
            }
        }
    }
}

// ---------------- layer-2: aggregate p, add q, sigmoid, store ----------------
__global__ void k_aggout(const float* __restrict__ b2, float* __restrict__ out) {
    int i = blockIdx.x * blockDim.x + threadIdx.x;
    if (i >= N_NODES) return;
    int beg = g_rowptr[i], end = g_rowptr[i + 1];
    float a0 = 0.f, a1 = 0.f;
    const float2* p2 = (const float2*)g_p;
    for (int j = beg; j < end; j++) {
        float2 v = p2[g_nbr[j]];
        a0 += v.x; a1 += v.y;
    }
    float id = g_invdeg[i];
    float v0 = a0 * id + g_q[i * 2 + 0] + b2[0];
    float v1 = a1 * id + g_q[i * 2 + 1] + b2[1];
    out[i * 2 + 0] = 1.0f / (1.0f + __expf(-v0));
    out[i * 2 + 1] = 1.0f / (1.0f + __expf(-v1));
}

// ---------------- launch ------------------------------------------------------
extern "C" void kernel_launch(void* const* d_in, const int* in_sizes, int n_in,
                              void* d_out, int out_size) {
    const float* x   = (const float*)d_in[0];
    const int*   ei  = (const int*)d_in[1];
    const float* W1l = (const float*)d_in[2];
    const float* W1r = (const float*)d_in[3];
    const float* b1  = (const float*)d_in[4];
    const float* W2l = (const float*)d_in[5];
    const float* W2r = (const float*)d_in[6];
    const float* b2  = (const float*)d_in[7];

    float* out = (float*)d_out;
    float* emb = out + (size_t)N_NODES * 2;

    const int* src = ei;
    const int* dst = ei + N_EDGES;

    cudaFuncSetAttribute(k_gemm1_mma, cudaFuncAttributeMaxDynamicSharedMemorySize, SM_TOT);

    // conversions + zeroing (independent of CSR)
    k_convW<<<(256 * 256 + 255) / 256, 256>>>(W1l, W1r);
    k_convx<<<(N_NODES * 32 + 255) / 256, 256>>>(x);
    k_zero<<<(N_NODES * 2 + 255) / 256, 256>>>();

    // CSR build
    k_hist<<<(N_EDGES + 255) / 256, 256>>>(dst);
    k_scan<<<1, 1024>>>();
    k_scatter<<<(N_EDGES + 255) / 256, 256>>>(src, dst);

    // layer 1 aggregation + A conversion
    k_agg1c<<<(N_NODES + 7) / 8, 256>>>(x);

    // layer-1 GEMM (HMMA) + fused layer-2 projections
    dim3 g1(M_TILES, 2);
    k_gemm1_mma<<<g1, 256, SM_TOT>>>(b1, W2l, W2r, emb);

    // layer-2: aggregate 2-dim projections + output
    k_aggout<<<(N_NODES + 255) / 256, 256>>>(b2, out);
}

// round 8
// speedup vs baseline: 1.7317x; 1.2811x over previous
#include <cuda_runtime.h>
#include <cuda_fp16.h>
#include <cstdint>

#define N_NODES   50000
#define N_EDGES   800000
#define D_FEAT    128
#define HIDDEN    256
#define N_PAD     50048          // 391 * 128
#define M_TILES   391

// ---------------- scratch (static device globals) ---------------------------
__device__ int   g_deg[N_NODES];
__device__ int   g_rowptr[N_NODES + 1];
__device__ int   g_cursor[N_NODES];
__device__ float g_invdeg[N_NODES];
__device__ int   g_nbr[N_EDGES];
__device__ __half g_A[(size_t)N_PAD * 256];   // [mean|x] fp16; pad rows stay 0
__device__ __half g_B[256 * 256];             // B^T: [n][k], k-major, fp16
__device__ float g_p[N_NODES * 2];   // h @ W2l (atomic-accumulated)
__device__ float g_q[N_NODES * 2];   // h @ W2r

// ---------------- prep: zero deg/p/q + convert W1 ----------------------------
__global__ void k_prep(const float* __restrict__ W1l, const float* __restrict__ W1r) {
    int i = blockIdx.x * blockDim.x + threadIdx.x;
    if (i < N_NODES) g_deg[i] = 0;
    if (i < N_NODES * 2) { g_p[i] = 0.f; g_q[i] = 0.f; }
    if (i < 256 * 256) {
        int k = i >> 8, n = i & 255;
        float v = (k < 128) ? W1l[k * 256 + n] : W1r[(k - 128) * 256 + n];
        g_B[n * 256 + k] = __float2half_rn(v);
    }
}

__global__ void k_hist(const int* __restrict__ dst) {
    int e = blockIdx.x * blockDim.x + threadIdx.x;
    if (e < N_EDGES) atomicAdd(&g_deg[dst[e]], 1);
}

// 1 block, 1024 threads = 32 warps, warp-coalesced coarsened scan
__global__ void k_scan() {
    const int ROUNDS = 49;              // 49*32 = 1568 per warp; 32*1568 = 50176
    __shared__ int warp_tot[32];
    int tid = threadIdx.x, lane = tid & 31, wid = tid >> 5;
    int base = wid * (ROUNDS * 32);

    int s = 0;
#pragma unroll 7
    for (int j = 0; j < ROUNDS; j++) {
        int idx = base + j * 32 + lane;
        if (idx < N_NODES) s += g_deg[idx];
    }
#pragma unroll
    for (int o = 16; o > 0; o >>= 1) s += __shfl_xor_sync(0xffffffffu, s, o);
    if (lane == 0) warp_tot[wid] = s;
    __syncthreads();
    if (wid == 0) {
        int w = warp_tot[lane];
        int xw = w;
#pragma unroll
        for (int o = 1; o < 32; o <<= 1) {
            int t = __shfl_up_sync(0xffffffffu, xw, o);
            if (lane >= o) xw += t;
        }
        warp_tot[lane] = xw;
    }
    __syncthreads();
    int carry = (wid > 0) ? warp_tot[wid - 1] : 0;

#pragma unroll 7
    for (int j = 0; j < ROUNDS; j++) {
        int idx = base + j * 32 + lane;
        int v = (idx < N_NODES) ? g_deg[idx] : 0;
        int xv = v;
#pragma unroll
        for (int o = 1; o < 32; o <<= 1) {
            int t = __shfl_up_sync(0xffffffffu, xv, o);
            if (lane >= o) xv += t;
        }
        int excl = carry + xv - v;
        if (idx < N_NODES) {
            g_rowptr[idx] = excl;
            g_cursor[idx] = excl;
            g_invdeg[idx] = 1.0f / (float)(v > 0 ? v : 1);
        }
        carry += __shfl_sync(0xffffffffu, xv, 31);
    }
    if (wid == 31 && lane == 31) g_rowptr[N_NODES] = carry;
}
__global__ void k_scatter(const int* __restrict__ src, const int* __restrict__ dst) {
    int e = blockIdx.x * blockDim.x + threadIdx.x;
    if (e < N_EDGES) {
        int d = dst[e];
        int pos = atomicAdd(&g_cursor[d], 1);
        g_nbr[pos] = src[e];
    }
}

// ---------------- conversions -------------------------------------------------
// x into A cols [128,256)
__global__ void k_convx(const float* __restrict__ x) {
    int i = blockIdx.x * blockDim.x + threadIdx.x;
    if (i >= N_NODES * 32) return;
    int node = i >> 5, lane = i & 31;
    float4 v = *(const float4*)(x + (size_t)node * D_FEAT + lane * 4);
    uint2 pk;
    __half2 p0 = __floats2half2_rn(v.x, v.y);
    __half2 p1 = __floats2half2_rn(v.z, v.w);
    pk.x = *(uint32_t*)&p0;
    pk.y = *(uint32_t*)&p1;
    size_t off = (size_t)node * 256 + 128 + lane * 4;
    *reinterpret_cast<uint2*>(&g_A[off]) = pk;
}

// agg layer1 (warp/node): mean into A cols [0,128)
__global__ void k_agg1c(const float* __restrict__ x) {
    int warp = (blockIdx.x * blockDim.x + threadIdx.x) >> 5;
    int lane = threadIdx.x & 31;
    if (warp >= N_NODES) return;
    int beg = g_rowptr[warp], end = g_rowptr[warp + 1];
    float4 acc = make_float4(0.f, 0.f, 0.f, 0.f);
    for (int j = beg; j < end; j++) {
        int s = g_nbr[j];
        float4 v = *(const float4*)(x + (size_t)s * D_FEAT + lane * 4);
        acc.x += v.x; acc.y += v.y; acc.z += v.z; acc.w += v.w;
    }
    float id = g_invdeg[warp];
    __half2 p0 = __floats2half2_rn(acc.x * id, acc.y * id);
    __half2 p1 = __floats2half2_rn(acc.z * id, acc.w * id);
    uint2 pk;
    pk.x = *(uint32_t*)&p0;
    pk.y = *(uint32_t*)&p1;
    size_t off = (size_t)warp * 256 + lane * 4;
    *reinterpret_cast<uint2*>(&g_A[off]) = pk;
}

// ---------------- HMMA GEMM1 (fp16, single-precision path) -------------------
// block tile 128x128, 8 warps = 4(M) x 2(N), warp tile 32x64, K: 4 chunks of 64
// smem rows: 72 halves (144B) stride
__device__ __forceinline__ void mma_f16(float* d, const uint32_t* a,
                                        uint32_t b0, uint32_t b1) {
    asm volatile(
        "mma.sync.aligned.m16n8k16.row.col.f32.f16.f16.f32 "
        "{%0,%1,%2,%3}, {%4,%5,%6,%7}, {%8,%9}, {%0,%1,%2,%3};"
        : "+f"(d[0]), "+f"(d[1]), "+f"(d[2]), "+f"(d[3])
        : "r"(a[0]), "r"(a[1]), "r"(a[2]), "r"(a[3]), "r"(b0), "r"(b1));
}

__global__ void __launch_bounds__(256)
k_gemm1_mma(const float* __restrict__ b1,
            const float* __restrict__ W2l, const float* __restrict__ W2r,
            float* __restrict__ h) {
    __shared__ char smA[18432];        // 128 rows x 144B
    __shared__ char smB[18432];        // 128 n-rows x 144B
    __shared__ float bias[128];
    __shared__ float2 w2l[128];
    __shared__ float2 w2r[128];

    int tid  = threadIdx.x, lane = tid & 31, warp = tid >> 5;
    int warpM = warp & 3, warpN = warp >> 2;
    int m0 = blockIdx.x * 128, n0 = blockIdx.y * 128;

    if (tid < 128) {
        bias[tid] = b1[n0 + tid];
        w2l[tid]  = ((const float2*)W2l)[n0 + tid];
        w2r[tid]  = ((const float2*)W2r)[n0 + tid];
    }

    float acc[2][8][4];
#pragma unroll
    for (int mt = 0; mt < 2; mt++)
#pragma unroll
        for (int nt = 0; nt < 8; nt++)
#pragma unroll
            for (int j = 0; j < 4; j++) acc[mt][nt][j] = 0.f;

#pragma unroll 1
    for (int c = 0; c < 4; c++) {
        __syncthreads();
#pragma unroll
        for (int t = 0; t < 4; t++) {
            int idx = tid + t * 256;
            int r = idx >> 3, q = idx & 7;
            size_t ga = (size_t)(m0 + r) * 256 + c * 64 + q * 8;
            size_t gb = (size_t)(n0 + r) * 256 + c * 64 + q * 8;
            uint32_t so = (uint32_t)(r * 144 + q * 16);
            *(uint4*)(smA + so) = *(const uint4*)(g_A + ga);
            *(uint4*)(smB + so) = *(const uint4*)(g_B + gb);
        }
        __syncthreads();
#pragma unroll
        for (int s = 0; s < 4; s++) {
            int kb = s * 16 + (lane & 3) * 2;
            int ar = warpM * 32 + (lane >> 2);
            uint32_t a[2][4];
#pragma unroll
            for (int mt = 0; mt < 2; mt++) {
                int r0 = ar + mt * 16;
                uint32_t o00 = (uint32_t)(r0 * 144 + kb * 2);
                uint32_t o10 = o00 + 8 * 144;
                a[mt][0] = *(const uint32_t*)(smA + o00);
                a[mt][1] = *(const uint32_t*)(smA + o10);
                a[mt][2] = *(const uint32_t*)(smA + o00 + 16);
                a[mt][3] = *(const uint32_t*)(smA + o10 + 16);
            }
#pragma unroll
            for (int nt = 0; nt < 8; nt++) {
                int bn = warpN * 64 + nt * 8 + (lane >> 2);
                uint32_t bo = (uint32_t)(bn * 144 + kb * 2);
                uint32_t b0 = *(const uint32_t*)(smB + bo);
                uint32_t b1v = *(const uint32_t*)(smB + bo + 16);
#pragma unroll
                for (int mt = 0; mt < 2; mt++)
                    mma_f16(acc[mt][nt], a[mt], b0, b1v);
            }
        }
    }

    // epilogue: bias + relu + store h; fused projections p = h@W2l, q = h@W2r
#pragma unroll
    for (int mt = 0; mt < 2; mt++) {
        int rowA = m0 + warpM * 32 + mt * 16 + (lane >> 2);
        int rowB = rowA + 8;
        float pla0 = 0.f, pla1 = 0.f, pra0 = 0.f, pra1 = 0.f;
        float plb0 = 0.f, plb1 = 0.f, prb0 = 0.f, prb1 = 0.f;
#pragma unroll
        for (int nt = 0; nt < 8; nt++) {
            int cl = warpN * 64 + nt * 8 + (lane & 3) * 2;
            float bz0 = bias[cl], bz1 = bias[cl + 1];
            float h0 = fmaxf(acc[mt][nt][0] + bz0, 0.f);
            float h1 = fmaxf(acc[mt][nt][1] + bz1, 0.f);
            float h2 = fmaxf(acc[mt][nt][2] + bz0, 0.f);
            float h3 = fmaxf(acc[mt][nt][3] + bz1, 0.f);
            if (rowA < N_NODES)
                *(float2*)(h + (size_t)rowA * 256 + n0 + cl) = make_float2(h0, h1);
            if (rowB < N_NODES)
                *(float2*)(h + (size_t)rowB * 256 + n0 + cl) = make_float2(h2, h3);
            float2 wl0 = w2l[cl], wl1 = w2l[cl + 1];
            float2 wr0 = w2r[cl], wr1 = w2r[cl + 1];
            pla0 += h0 * wl0.x + h1 * wl1.x;  pla1 += h0 * wl0.y + h1 * wl1.y;
            pra0 += h0 * wr0.x + h1 * wr1.x;  pra1 += h0 * wr0.y + h1 * wr1.y;
            plb0 += h2 * wl0.x + h3 * wl1.x;  plb1 += h2 * wl0.y + h3 * wl1.y;
            prb0 += h2 * wr0.x + h3 * wr1.x;  prb1 += h2 * wr0.y + h3 * wr1.y;
        }
#pragma unroll
        for (int o = 1; o <= 2; o <<= 1) {
            pla0 += __shfl_xor_sync(0xffffffffu, pla0, o);
            pla1 += __shfl_xor_sync(0xffffffffu, pla1, o);
            pra0 += __shfl_xor_sync(0xffffffffu, pra0, o);
            pra1 += __shfl_xor_sync(0xffffffffu, pra1, o);
            plb0 += __shfl_xor_sync(0xffffffffu, plb0, o);
            plb1 += __shfl_xor_sync(0xffffffffu, plb1, o);
            prb0 += __shfl_xor_sync(0xffffffffu, prb0, o);
            prb1 += __shfl_xor_sync(0xffffffffu, prb1, o);
        }
        if ((lane & 3) == 0) {
            if (rowA < N_NODES) {
                atomicAdd(&g_p[rowA * 2 + 0], pla0);
                atomicAdd(&g_p[rowA * 2 + 1], pla1);
                atomicAdd(&g_q[rowA * 2 + 0], pra0);
                atomicAdd(&g_q[rowA * 2 + 1], pra1);
            }
            if (rowB < N_NODES) {
                atomicAdd(&g_p[rowB * 2 + 0], plb0);
                atomicAdd(&g_p[rowB * 2 + 1], plb1);
                atomicAdd(&g_q[rowB * 2 + 0], prb0);
                atomicAdd(&g_q[rowB * 2 + 1], prb1);
            }
        }
    }
}

// ---------------- layer-2: aggregate p, add q, sigmoid, store ----------------
__global__ void k_aggout(const float* __restrict__ b2, float* __restrict__ out) {
    int i = blockIdx.x * blockDim.x + threadIdx.x;
    if (i >= N_NODES) return;
    int beg = g_rowptr[i], end = g_rowptr[i + 1];
    float a0 = 0.f, a1 = 0.f;
    const float2* p2 = (const float2*)g_p;
    for (int j = beg; j < end; j++) {
        float2 v = p2[g_nbr[j]];
        a0 += v.x; a1 += v.y;
    }
    float id = g_invdeg[i];
    float v0 = a0 * id + g_q[i * 2 + 0] + b2[0];
    float v1 = a1 * id + g_q[i * 2 + 1] + b2[1];
    out[i * 2 + 0] = 1.0f / (1.0f + __expf(-v0));
    out[i * 2 + 1] = 1.0f / (1.0f + __expf(-v1));
}

// ---------------- launch ------------------------------------------------------
extern "C" void kernel_launch(void* const* d_in, const int* in_sizes, int n_in,
                              void* d_out, int out_size) {
    const float* x   = (const float*)d_in[0];
    const int*   ei  = (const int*)d_in[1];
    const float* W1l = (const float*)d_in[2];
    const float* W1r = (const float*)d_in[3];
    const float* b1  = (const float*)d_in[4];
    const float* W2l = (const float*)d_in[5];
    const float* W2r = (const float*)d_in[6];
    const float* b2  = (const float*)d_in[7];

    float* out = (float*)d_out;
    float* emb = out + (size_t)N_NODES * 2;

    const int* src = ei;
    const int* dst = ei + N_EDGES;

    // prep: zero deg/p/q + convert W1 (one kernel)
    k_prep<<<(N_NODES * 2 + 255) / 256, 256>>>(W1l, W1r);
    k_convx<<<(N_NODES * 32 + 255) / 256, 256>>>(x);

    // CSR build
    k_hist<<<(N_EDGES + 255) / 256, 256>>>(dst);
    k_scan<<<1, 1024>>>();
    k_scatter<<<(N_EDGES + 255) / 256, 256>>>(src, dst);

    // layer 1 aggregation + A conversion
    k_agg1c<<<(N_NODES + 7) / 8, 256>>>(x);

    // layer-1 GEMM (fp16 HMMA) + fused layer-2 projections
    dim3 g1(M_TILES, 2);
    k_gemm1_mma<<<g1, 256>>>(b1, W2l, W2r, emb);

    // layer-2: aggregate 2-dim projections + output
    k_aggout<<<(N_NODES + 255) / 256, 256>>>(b2, out);
}

// round 9
// speedup vs baseline: 2.3193x; 1.3393x over previous
#include <cuda_runtime.h>
#include <cuda_fp16.h>
#include <cstdint>

#define N_NODES   50000
#define N_EDGES   800000
#define D_FEAT    128
#define HIDDEN    256
#define N_PAD     50048          // 391 * 128
#define M_TILES   391
#define SCAN_BLKS 49             // 49 * 1024 = 50176 >= N_NODES

// ---------------- scratch (static device globals) ---------------------------
__device__ int   g_deg[N_NODES];
__device__ int   g_blksum[SCAN_BLKS];
__device__ int   g_rowptr[N_NODES + 1];
__device__ int   g_cursor[N_NODES];
__device__ float g_invdeg[N_NODES];
__device__ int   g_nbr[N_EDGES];
__device__ __half g_A[(size_t)N_PAD * 256];   // [mean|x] fp16; pad rows stay 0
__device__ __half g_B[256 * 256];             // B^T: [n][k], k-major, fp16
__device__ float g_p[N_NODES * 2];   // h @ W2l (atomic-accumulated)
__device__ float g_q[N_NODES * 2];   // h @ W2r

// ---------------- prep: zero deg/p/q + convert W1 ----------------------------
__global__ void k_prep(const float* __restrict__ W1l, const float* __restrict__ W1r) {
    int i = blockIdx.x * blockDim.x + threadIdx.x;
    if (i < N_NODES) g_deg[i] = 0;
    if (i < N_NODES * 2) { g_p[i] = 0.f; g_q[i] = 0.f; }
    if (i < 256 * 256) {
        int k = i >> 8, n = i & 255;
        float v = (k < 128) ? W1l[k * 256 + n] : W1r[(k - 128) * 256 + n];
        g_B[n * 256 + k] = __float2half_rn(v);
    }
}

__global__ void k_hist(const int* __restrict__ dst) {
    int e = blockIdx.x * blockDim.x + threadIdx.x;
    if (e < N_EDGES) atomicAdd(&g_deg[dst[e]], 1);
}

// ---- scan phase A: per-block (1024-chunk) reduction ----
__global__ void k_scanA() {
    __shared__ int wsum[32];
    int tid = threadIdx.x, lane = tid & 31, wid = tid >> 5;
    int idx = blockIdx.x * 1024 + tid;
    int v = (idx < N_NODES) ? g_deg[idx] : 0;
#pragma unroll
    for (int o = 16; o > 0; o >>= 1) v += __shfl_xor_sync(0xffffffffu, v, o);
    if (lane == 0) wsum[wid] = v;
    __syncthreads();
    if (wid == 0) {
        int s = wsum[lane];
#pragma unroll
        for (int o = 16; o > 0; o >>= 1) s += __shfl_xor_sync(0xffffffffu, s, o);
        if (lane == 0) g_blksum[blockIdx.x] = s;
    }
}

// ---- scan phase B: block base from blksums + block-local scan + writes ----
__global__ void k_scanB() {
    __shared__ int warp_tot[32];
    __shared__ int s_base;
    int tid = threadIdx.x, lane = tid & 31, wid = tid >> 5;
    int bid = blockIdx.x;

    if (wid == 0) {
        int v0 = (lane < bid) ? g_blksum[lane] : 0;
        int v1 = (lane + 32 < bid) ? g_blksum[lane + 32] : 0;
        int s = v0 + v1;
#pragma unroll
        for (int o = 16; o > 0; o >>= 1) s += __shfl_xor_sync(0xffffffffu, s, o);
        if (lane == 0) s_base = s;
    }

    int idx = bid * 1024 + tid;
    int v = (idx < N_NODES) ? g_deg[idx] : 0;
    int xv = v;
#pragma unroll
    for (int o = 1; o < 32; o <<= 1) {
        int t = __shfl_up_sync(0xffffffffu, xv, o);
        if (lane >= o) xv += t;
    }
    if (lane == 31) warp_tot[wid] = xv;
    __syncthreads();
    if (wid == 0) {
        int w = warp_tot[lane];
        int xw = w;
#pragma unroll
        for (int o = 1; o < 32; o <<= 1) {
            int t = __shfl_up_sync(0xffffffffu, xw, o);
            if (lane >= o) xw += t;
        }
        warp_tot[lane] = xw;            // inclusive warp totals
    }
    __syncthreads();
    int base = s_base + ((wid > 0) ? warp_tot[wid - 1] : 0);
    int excl = base + xv - v;
    if (idx < N_NODES) {
        g_rowptr[idx] = excl;
        g_cursor[idx] = excl;
        g_invdeg[idx] = 1.0f / (float)(v > 0 ? v : 1);
    }
    if (bid == SCAN_BLKS - 1 && tid == 1023)
        g_rowptr[N_NODES] = s_base + warp_tot[31];
}

__global__ void k_scatter(const int* __restrict__ src, const int* __restrict__ dst) {
    int e = blockIdx.x * blockDim.x + threadIdx.x;
    if (e < N_EDGES) {
        int d = dst[e];
        int pos = atomicAdd(&g_cursor[d], 1);
        g_nbr[pos] = src[e];
    }
}

// ---------------- conversions -------------------------------------------------
// x into A cols [128,256)
__global__ void k_convx(const float* __restrict__ x) {
    int i = blockIdx.x * blockDim.x + threadIdx.x;
    if (i >= N_NODES * 32) return;
    int node = i >> 5, lane = i & 31;
    float4 v = *(const float4*)(x + (size_t)node * D_FEAT + lane * 4);
    uint2 pk;
    __half2 p0 = __floats2half2_rn(v.x, v.y);
    __half2 p1 = __floats2half2_rn(v.z, v.w);
    pk.x = *(uint32_t*)&p0;
    pk.y = *(uint32_t*)&p1;
    size_t off = (size_t)node * 256 + 128 + lane * 4;
    *reinterpret_cast<uint2*>(&g_A[off]) = pk;
}

// agg layer1 (warp/node): mean of fp16 x (read from g_A x-half) into cols [0,128)
__global__ void k_agg1c() {
    int warp = (blockIdx.x * blockDim.x + threadIdx.x) >> 5;
    int lane = threadIdx.x & 31;
    if (warp >= N_NODES) return;
    int beg = g_rowptr[warp], end = g_rowptr[warp + 1];
    float4 acc = make_float4(0.f, 0.f, 0.f, 0.f);
    for (int j = beg; j < end; j++) {
        int s = g_nbr[j];
        uint2 pk = *reinterpret_cast<const uint2*>(g_A + (size_t)s * 256 + 128 + lane * 4);
        float2 f0 = __half22float2(*(const __half2*)&pk.x);
        float2 f1 = __half22float2(*(const __half2*)&pk.y);
        acc.x += f0.x; acc.y += f0.y; acc.z += f1.x; acc.w += f1.y;
    }
    float id = g_invdeg[warp];
    __half2 p0 = __floats2half2_rn(acc.x * id, acc.y * id);
    __half2 p1 = __floats2half2_rn(acc.z * id, acc.w * id);
    uint2 pk;
    pk.x = *(uint32_t*)&p0;
    pk.y = *(uint32_t*)&p1;
    size_t off = (size_t)warp * 256 + lane * 4;
    *reinterpret_cast<uint2*>(&g_A[off]) = pk;
}

// ---------------- HMMA GEMM1 (fp16) + fused layer-2 projections --------------
// block tile 128x128, 8 warps = 4(M) x 2(N), warp tile 32x64, K: 4 chunks of 64
__device__ __forceinline__ void mma_f16(float* d, const uint32_t* a,
                                        uint32_t b0, uint32_t b1) {
    asm volatile(
        "mma.sync.aligned.m16n8k16.row.col.f32.f16.f16.f32 "
        "{%0,%1,%2,%3}, {%4,%5,%6,%7}, {%8,%9}, {%0,%1,%2,%3};"
        : "+f"(d[0]), "+f"(d[1]), "+f"(d[2]), "+f"(d[3])
        : "r"(a[0]), "r"(a[1]), "r"(a[2]), "r"(a[3]), "r"(b0), "r"(b1));
}

__global__ void __launch_bounds__(256)
k_gemm1_mma(const float* __restrict__ b1,
            const float* __restrict__ W2l, const float* __restrict__ W2r,
            float* __restrict__ h) {
    __shared__ char smA[18432];        // 128 rows x 144B
    __shared__ char smB[18432];
    __shared__ float bias[128];
    __shared__ float2 w2l[128];
    __shared__ float2 w2r[128];

    int tid  = threadIdx.x, lane = tid & 31, warp = tid >> 5;
    int warpM = warp & 3, warpN = warp >> 2;
    int m0 = blockIdx.x * 128, n0 = blockIdx.y * 128;

    if (tid < 128) {
        bias[tid] = b1[n0 + tid];
        w2l[tid]  = ((const float2*)W2l)[n0 + tid];
        w2r[tid]  = ((const float2*)W2r)[n0 + tid];
    }

    float acc[2][8][4];
#pragma unroll
    for (int mt = 0; mt < 2; mt++)
#pragma unroll
        for (int nt = 0; nt < 8; nt++)
#pragma unroll
            for (int j = 0; j < 4; j++) acc[mt][nt][j] = 0.f;

#pragma unroll 1
    for (int c = 0; c < 4; c++) {
        __syncthreads();
#pragma unroll
        for (int t = 0; t < 4; t++) {
            int idx = tid + t * 256;
            int r = idx >> 3, q = idx & 7;
            size_t ga = (size_t)(m0 + r) * 256 + c * 64 + q * 8;
            size_t gb = (size_t)(n0 + r) * 256 + c * 64 + q * 8;
            uint32_t so = (uint32_t)(r * 144 + q * 16);
            *(uint4*)(smA + so) = *(const uint4*)(g_A + ga);
            *(uint4*)(smB + so) = *(const uint4*)(g_B + gb);
        }
        __syncthreads();
#pragma unroll
        for (int s = 0; s < 4; s++) {
            int kb = s * 16 + (lane & 3) * 2;
            int ar = warpM * 32 + (lane >> 2);
            uint32_t a[2][4];
#pragma unroll
            for (int mt = 0; mt < 2; mt++) {
                int r0 = ar + mt * 16;
                uint32_t o00 = (uint32_t)(r0 * 144 + kb * 2);
                uint32_t o10 = o00 + 8 * 144;
                a[mt][0] = *(const uint32_t*)(smA + o00);
                a[mt][1] = *(const uint32_t*)(smA + o10);
                a[mt][2] = *(const uint32_t*)(smA + o00 + 16);
                a[mt][3] = *(const uint32_t*)(smA + o10 + 16);
            }
#pragma unroll
            for (int nt = 0; nt < 8; nt++) {
                int bn = warpN * 64 + nt * 8 + (lane >> 2);
                uint32_t bo = (uint32_t)(bn * 144 + kb * 2);
                uint32_t b0 = *(const uint32_t*)(smB + bo);
                uint32_t b1v = *(const uint32_t*)(smB + bo + 16);
#pragma unroll
                for (int mt = 0; mt < 2; mt++)
                    mma_f16(acc[mt][nt], a[mt], b0, b1v);
            }
        }
    }

    // epilogue: bias + relu + store h; fused projections p = h@W2l, q = h@W2r
#pragma unroll
    for (int mt = 0; mt < 2; mt++) {
        int rowA = m0 + warpM * 32 + mt * 16 + (lane >> 2);
        int rowB = rowA + 8;
        float pla0 = 0.f, pla1 = 0.f, pra0 = 0.f, pra1 = 0.f;
        float plb0 = 0.f, plb1 = 0.f, prb0 = 0.f, prb1 = 0.f;
#pragma unroll
        for (int nt = 0; nt < 8; nt++) {
            int cl = warpN * 64 + nt * 8 + (lane & 3) * 2;
            float bz0 = bias[cl], bz1 = bias[cl + 1];
            float h0 = fmaxf(acc[mt][nt][0] + bz0, 0.f);
            float h1 = fmaxf(acc[mt][nt][1] + bz1, 0.f);
            float h2 = fmaxf(acc[mt][nt][2] + bz0, 0.f);
            float h3 = fmaxf(acc[mt][nt][3] + bz1, 0.f);
            if (rowA < N_NODES)
                *(float2*)(h + (size_t)rowA * 256 + n0 + cl) = make_float2(h0, h1);
            if (rowB < N_NODES)
                *(float2*)(h + (size_t)rowB * 256 + n0 + cl) = make_float2(h2, h3);
            float2 wl0 = w2l[cl], wl1 = w2l[cl + 1];
            float2 wr0 = w2r[cl], wr1 = w2r[cl + 1];
            pla0 += h0 * wl0.x + h1 * wl1.x;  pla1 += h0 * wl0.y + h1 * wl1.y;
            pra0 += h0 * wr0.x + h1 * wr1.x;  pra1 += h0 * wr0.y + h1 * wr1.y;
            plb0 += h2 * wl0.x + h3 * wl1.x;  plb1 += h2 * wl0.y + h3 * wl1.y;
            prb0 += h2 * wr0.x + h3 * wr1.x;  prb1 += h2 * wr0.y + h3 * wr1.y;
        }
#pragma unroll
        for (int o = 1; o <= 2; o <<= 1) {
            pla0 += __shfl_xor_sync(0xffffffffu, pla0, o);
            pla1 += __shfl_xor_sync(0xffffffffu, pla1, o);
            pra0 += __shfl_xor_sync(0xffffffffu, pra0, o);
            pra1 += __shfl_xor_sync(0xffffffffu, pra1, o);
            plb0 += __shfl_xor_sync(0xffffffffu, plb0, o);
            plb1 += __shfl_xor_sync(0xffffffffu, plb1, o);
            prb0 += __shfl_xor_sync(0xffffffffu, prb0, o);
            prb1 += __shfl_xor_sync(0xffffffffu, prb1, o);
        }
        if ((lane & 3) == 0) {
            if (rowA < N_NODES) {
                atomicAdd(&g_p[rowA * 2 + 0], pla0);
                atomicAdd(&g_p[rowA * 2 + 1], pla1);
                atomicAdd(&g_q[rowA * 2 + 0], pra0);
                atomicAdd(&g_q[rowA * 2 + 1], pra1);
            }
            if (rowB < N_NODES) {
                atomicAdd(&g_p[rowB * 2 + 0], plb0);
                atomicAdd(&g_p[rowB * 2 + 1], plb1);
                atomicAdd(&g_q[rowB * 2 + 0], prb0);
                atomicAdd(&g_q[rowB * 2 + 1], prb1);
            }
        }
    }
}

// ---------------- layer-2: aggregate p, add q, sigmoid, store ----------------
__global__ void k_aggout(const float* __restrict__ b2, float* __restrict__ out) {
    int i = blockIdx.x * blockDim.x + threadIdx.x;
    if (i >= N_NODES) return;
    int beg = g_rowptr[i], end = g_rowptr[i + 1];
    float a0 = 0.f, a1 = 0.f;
    const float2* p2 = (const float2*)g_p;
    for (int j = beg; j < end; j++) {
        float2 v = p2[g_nbr[j]];
        a0 += v.x; a1 += v.y;
    }
    float id = g_invdeg[i];
    float v0 = a0 * id + g_q[i * 2 + 0] + b2[0];
    float v1 = a1 * id + g_q[i * 2 + 1] + b2[1];
    out[i * 2 + 0] = 1.0f / (1.0f + __expf(-v0));
    out[i * 2 + 1] = 1.0f / (1.0f + __expf(-v1));
}

// ---------------- launch ------------------------------------------------------
extern "C" void kernel_launch(void* const* d_in, const int* in_sizes, int n_in,
                              void* d_out, int out_size) {
    const float* x   = (const float*)d_in[0];
    const int*   ei  = (const int*)d_in[1];
    const float* W1l = (const float*)d_in[2];
    const float* W1r = (const float*)d_in[3];
    const float* b1  = (const float*)d_in[4];
    const float* W2l = (const float*)d_in[5];
    const float* W2r = (const float*)d_in[6];
    const float* b2  = (const float*)d_in[7];

    float* out = (float*)d_out;
    float* emb = out + (size_t)N_NODES * 2;

    const int* src = ei;
    const int* dst = ei + N_EDGES;

    // prep: zero deg/p/q + convert W1; convert x to fp16
    k_prep<<<(N_NODES * 2 + 255) / 256, 256>>>(W1l, W1r);
    k_convx<<<(N_NODES * 32 + 255) / 256, 256>>>(x);

    // CSR build (multi-block scan)
    k_hist<<<(N_EDGES + 255) / 256, 256>>>(dst);
    k_scanA<<<SCAN_BLKS, 1024>>>();
    k_scanB<<<SCAN_BLKS, 1024>>>();
    k_scatter<<<(N_EDGES + 255) / 256, 256>>>(src, dst);

    // layer 1 aggregation (fp16 reads) + A conversion
    k_agg1c<<<(N_NODES + 7) / 8, 256>>>();

    // layer-1 GEMM (fp16 HMMA) + fused layer-2 projections
    dim3 g1(M_TILES, 2);
    k_gemm1_mma<<<g1, 256>>>(b1, W2l, W2r, emb);

    // layer-2: aggregate 2-dim projections + output
    k_aggout<<<(N_NODES + 255) / 256, 256>>>(b2, out);
}

// round 10
// speedup vs baseline: 2.3646x; 1.0195x over previous
#include <cuda_runtime.h>
#include <cuda_fp16.h>
#include <cstdint>

#define N_NODES   50000
#define N_EDGES   800000
#define D_FEAT    128
#define HIDDEN    256
#define N_PAD     50048          // 391 * 128
#define M_TILES   391
#define SCAN_BLKS 49             // 49 * 1024 = 50176 >= N_NODES

// ---------------- scratch (static device globals) ---------------------------
__device__ int   g_deg[N_NODES];
__device__ int   g_blksum[SCAN_BLKS];
__device__ int   g_rowptr[N_NODES + 1];
__device__ int   g_cursor[N_NODES];
__device__ float g_invdeg[N_NODES];
__device__ int   g_nbr[N_EDGES];
__device__ __half g_A[(size_t)N_PAD * 256];   // [mean|x] fp16; pad rows stay 0
__device__ __half g_B[256 * 256];             // B^T: [n][k], k-major, fp16
__device__ float g_p[N_NODES * 2];   // h @ W2l (atomic-accumulated)
__device__ float g_q[N_NODES * 2];   // h @ W2r

// ---------------- prep: zero deg/p/q + convert W1 + convert x ----------------
__global__ void k_prep(const float* __restrict__ W1l, const float* __restrict__ W1r,
                       const float* __restrict__ x) {
    int i = blockIdx.x * blockDim.x + threadIdx.x;
    if (i < N_NODES) g_deg[i] = 0;
    if (i < N_NODES * 2) { g_p[i] = 0.f; g_q[i] = 0.f; }
    if (i < 256 * 256) {
        int k = i >> 8, n = i & 255;
        float v = (k < 128) ? W1l[k * 256 + n] : W1r[(k - 128) * 256 + n];
        g_B[n * 256 + k] = __float2half_rn(v);
    }
    if (i < N_NODES * 32) {
        int node = i >> 5, lane = i & 31;
        float4 v = *(const float4*)(x + (size_t)node * D_FEAT + lane * 4);
        uint2 pk;
        __half2 p0 = __floats2half2_rn(v.x, v.y);
        __half2 p1 = __floats2half2_rn(v.z, v.w);
        pk.x = *(uint32_t*)&p0;
        pk.y = *(uint32_t*)&p1;
        size_t off = (size_t)node * 256 + 128 + lane * 4;
        *reinterpret_cast<uint2*>(&g_A[off]) = pk;
    }
}

__global__ void k_hist(const int* __restrict__ dst) {
    int e = blockIdx.x * blockDim.x + threadIdx.x;
    if (e < N_EDGES) atomicAdd(&g_deg[dst[e]], 1);
}

// ---- scan phase A: per-block (1024-chunk) reduction ----
__global__ void k_scanA() {
    __shared__ int wsum[32];
    int tid = threadIdx.x, lane = tid & 31, wid = tid >> 5;
    int idx = blockIdx.x * 1024 + tid;
    int v = (idx < N_NODES) ? g_deg[idx] : 0;
#pragma unroll
    for (int o = 16; o > 0; o >>= 1) v += __shfl_xor_sync(0xffffffffu, v, o);
    if (lane == 0) wsum[wid] = v;
    __syncthreads();
    if (wid == 0) {
        int s = wsum[lane];
#pragma unroll
        for (int o = 16; o > 0; o >>= 1) s += __shfl_xor_sync(0xffffffffu, s, o);
        if (lane == 0) g_blksum[blockIdx.x] = s;
    }
}

// ---- scan phase B: block base from blksums + block-local scan + writes ----
__global__ void k_scanB() {
    __shared__ int warp_tot[32];
    __shared__ int s_base;
    int tid = threadIdx.x, lane = tid & 31, wid = tid >> 5;
    int bid = blockIdx.x;

    if (wid == 0) {
        int v0 = (lane < bid) ? g_blksum[lane] : 0;
        int v1 = (lane + 32 < bid) ? g_blksum[lane + 32] : 0;
        int s = v0 + v1;
#pragma unroll
        for (int o = 16; o > 0; o >>= 1) s += __shfl_xor_sync(0xffffffffu, s, o);
        if (lane == 0) s_base = s;
    }

    int idx = bid * 1024 + tid;
    int v = (idx < N_NODES) ? g_deg[idx] : 0;
    int xv = v;
#pragma unroll
    for (int o = 1; o < 32; o <<= 1) {
        int t = __shfl_up_sync(0xffffffffu, xv, o);
        if (lane >= o) xv += t;
    }
    if (lane == 31) warp_tot[wid] = xv;
    __syncthreads();
    if (wid == 0) {
        int w = warp_tot[lane];
        int xw = w;
#pragma unroll
        for (int o = 1; o < 32; o <<= 1) {
            int t = __shfl_up_sync(0xffffffffu, xw, o);
            if (lane >= o) xw += t;
        }
        warp_tot[lane] = xw;            // inclusive warp totals
    }
    __syncthreads();
    int base = s_base + ((wid > 0) ? warp_tot[wid - 1] : 0);
    int excl = base + xv - v;
    if (idx < N_NODES) {
        g_rowptr[idx] = excl;
        g_cursor[idx] = excl;
        g_invdeg[idx] = 1.0f / (float)(v > 0 ? v : 1);
    }
    if (bid == SCAN_BLKS - 1 && tid == 1023)
        g_rowptr[N_NODES] = s_base + warp_tot[31];
}

__global__ void k_scatter(const int* __restrict__ src, const int* __restrict__ dst) {
    int e = blockIdx.x * blockDim.x + threadIdx.x;
    if (e < N_EDGES) {
        int d = dst[e];
        int pos = atomicAdd(&g_cursor[d], 1);
        g_nbr[pos] = src[e];
    }
}

// agg layer1 (warp/node): mean of fp16 x (read from g_A x-half) into cols [0,128)
__global__ void k_agg1c() {
    int warp = (blockIdx.x * blockDim.x + threadIdx.x) >> 5;
    int lane = threadIdx.x & 31;
    if (warp >= N_NODES) return;
    int beg = g_rowptr[warp], end = g_rowptr[warp + 1];
    float4 acc = make_float4(0.f, 0.f, 0.f, 0.f);
    for (int j = beg; j < end; j++) {
        int s = g_nbr[j];
        uint2 pk = *reinterpret_cast<const uint2*>(g_A + (size_t)s * 256 + 128 + lane * 4);
        float2 f0 = __half22float2(*(const __half2*)&pk.x);
        float2 f1 = __half22float2(*(const __half2*)&pk.y);
        acc.x += f0.x; acc.y += f0.y; acc.z += f1.x; acc.w += f1.y;
    }
    float id = g_invdeg[warp];
    __half2 p0 = __floats2half2_rn(acc.x * id, acc.y * id);
    __half2 p1 = __floats2half2_rn(acc.z * id, acc.w * id);
    uint2 pk;
    pk.x = *(uint32_t*)&p0;
    pk.y = *(uint32_t*)&p1;
    size_t off = (size_t)warp * 256 + lane * 4;
    *reinterpret_cast<uint2*>(&g_A[off]) = pk;
}

// ---------------- HMMA GEMM1 (fp16, ldmatrix) + fused layer-2 projections ----
// block tile 128x128, 8 warps = 4(M) x 2(N), warp tile 32x64, K: 4 chunks of 64
__device__ __forceinline__ uint32_t smem_u32(const void* p) {
    uint32_t a;
    asm("{ .reg .u64 t; cvta.to.shared.u64 t, %1; cvt.u32.u64 %0, t; }" : "=r"(a) : "l"(p));
    return a;
}
__device__ __forceinline__ void ldm_x4(uint32_t* r, uint32_t addr) {
    asm volatile("ldmatrix.sync.aligned.m8n8.x4.shared.b16 {%0,%1,%2,%3}, [%4];"
        : "=r"(r[0]), "=r"(r[1]), "=r"(r[2]), "=r"(r[3]) : "r"(addr));
}
__device__ __forceinline__ void mma_f16(float* d, const uint32_t* a,
                                        uint32_t b0, uint32_t b1) {
    asm volatile(
        "mma.sync.aligned.m16n8k16.row.col.f32.f16.f16.f32 "
        "{%0,%1,%2,%3}, {%4,%5,%6,%7}, {%8,%9}, {%0,%1,%2,%3};"
        : "+f"(d[0]), "+f"(d[1]), "+f"(d[2]), "+f"(d[3])
        : "r"(a[0]), "r"(a[1]), "r"(a[2]), "r"(a[3]), "r"(b0), "r"(b1));
}

__global__ void __launch_bounds__(256)
k_gemm1_mma(const float* __restrict__ b1,
            const float* __restrict__ W2l, const float* __restrict__ W2r,
            float* __restrict__ h) {
    __shared__ char smA[18432];        // 128 rows x 144B
    __shared__ char smB[18432];
    __shared__ float bias[128];
    __shared__ float2 w2l[128];
    __shared__ float2 w2r[128];

    int tid  = threadIdx.x, lane = tid & 31, warp = tid >> 5;
    int warpM = warp & 3, warpN = warp >> 2;
    int m0 = blockIdx.x * 128, n0 = blockIdx.y * 128;
    uint32_t sA = smem_u32(smA), sB = smem_u32(smB);

    if (tid < 128) {
        bias[tid] = b1[n0 + tid];
        w2l[tid]  = ((const float2*)W2l)[n0 + tid];
        w2r[tid]  = ((const float2*)W2r)[n0 + tid];
    }

    float acc[2][8][4];
#pragma unroll
    for (int mt = 0; mt < 2; mt++)
#pragma unroll
        for (int nt = 0; nt < 8; nt++)
#pragma unroll
            for (int j = 0; j < 4; j++) acc[mt][nt][j] = 0.f;

#pragma unroll 1
    for (int c = 0; c < 4; c++) {
        __syncthreads();
#pragma unroll
        for (int t = 0; t < 4; t++) {
            int idx = tid + t * 256;
            int r = idx >> 3, q = idx & 7;
            size_t ga = (size_t)(m0 + r) * 256 + c * 64 + q * 8;
            size_t gb = (size_t)(n0 + r) * 256 + c * 64 + q * 8;
            uint32_t so = (uint32_t)(r * 144 + q * 16);
            *(uint4*)(smA + so) = *(const uint4*)(g_A + ga);
            *(uint4*)(smB + so) = *(const uint4*)(g_B + gb);
        }
        __syncthreads();
#pragma unroll
        for (int s = 0; s < 4; s++) {
            // A fragments via ldmatrix.x4 (mapping validated in R5)
            uint32_t a[2][4];
#pragma unroll
            for (int mt = 0; mt < 2; mt++) {
                int row = warpM * 32 + mt * 16 + (lane & 15);
                uint32_t off = (uint32_t)(row * 144 + (s * 16 + (lane >> 4) * 8) * 2);
                ldm_x4(a[mt], sA + off);
            }
            // B fragments via ldmatrix.x4: pr covers 16 n-rows
            uint32_t b[4][4];
#pragma unroll
            for (int pr = 0; pr < 4; pr++) {
                int nrow = warpN * 64 + pr * 16 + ((lane >> 4) ? 8 : 0) + (lane & 7);
                int koff = s * 16 + (((lane >> 3) & 1) * 8);
                uint32_t off = (uint32_t)(nrow * 144 + koff * 2);
                ldm_x4(b[pr], sB + off);
            }
#pragma unroll
            for (int pr = 0; pr < 4; pr++) {
#pragma unroll
                for (int hf = 0; hf < 2; hf++) {
                    int nt = pr * 2 + hf;
                    uint32_t b0 = b[pr][hf * 2], b1v = b[pr][hf * 2 + 1];
#pragma unroll
                    for (int mt = 0; mt < 2; mt++)
                        mma_f16(acc[mt][nt], a[mt], b0, b1v);
                }
            }
        }
    }

    // epilogue: bias + relu + store h; fused projections p = h@W2l, q = h@W2r
#pragma unroll
    for (int mt = 0; mt < 2; mt++) {
        int rowA = m0 + warpM * 32 + mt * 16 + (lane >> 2);
        int rowB = rowA + 8;
        float pla0 = 0.f, pla1 = 0.f, pra0 = 0.f, pra1 = 0.f;
        float plb0 = 0.f, plb1 = 0.f, prb0 = 0.f, prb1 = 0.f;
#pragma unroll
        for (int nt = 0; nt < 8; nt++) {
            int cl = warpN * 64 + nt * 8 + (lane & 3) * 2;
            float bz0 = bias[cl], bz1 = bias[cl + 1];
            float h0 = fmaxf(acc[mt][nt][0] + bz0, 0.f);
            float h1 = fmaxf(acc[mt][nt][1] + bz1, 0.f);
            float h2 = fmaxf(acc[mt][nt][2] + bz0, 0.f);
            float h3 = fmaxf(acc[mt][nt][3] + bz1, 0.f);
            if (rowA < N_NODES)
                *(float2*)(h + (size_t)rowA * 256 + n0 + cl) = make_float2(h0, h1);
            if (rowB < N_NODES)
                *(float2*)(h + (size_t)rowB * 256 + n0 + cl) = make_float2(h2, h3);
            float2 wl0 = w2l[cl], wl1 = w2l[cl + 1];
            float2 wr0 = w2r[cl], wr1 = w2r[cl + 1];
            pla0 += h0 * wl0.x + h1 * wl1.x;  pla1 += h0 * wl0.y + h1 * wl1.y;
            pra0 += h0 * wr0.x + h1 * wr1.x;  pra1 += h0 * wr0.y + h1 * wr1.y;
            plb0 += h2 * wl0.x + h3 * wl1.x;  plb1 += h2 * wl0.y + h3 * wl1.y;
            prb0 += h2 * wr0.x + h3 * wr1.x;  prb1 += h2 * wr0.y + h3 * wr1.y;
        }
#pragma unroll
        for (int o = 1; o <= 2; o <<= 1) {
            pla0 += __shfl_xor_sync(0xffffffffu, pla0, o);
            pla1 += __shfl_xor_sync(0xffffffffu, pla1, o);
            pra0 += __shfl_xor_sync(0xffffffffu, pra0, o);
            pra1 += __shfl_xor_sync(0xffffffffu, pra1, o);
            plb0 += __shfl_xor_sync(0xffffffffu, plb0, o);
            plb1 += __shfl_xor_sync(0xffffffffu, plb1, o);
            prb0 += __shfl_xor_sync(0xffffffffu, prb0, o);
            prb1 += __shfl_xor_sync(0xffffffffu, prb1, o);
        }
        if ((lane & 3) == 0) {
            if (rowA < N_NODES) {
                atomicAdd(&g_p[rowA * 2 + 0], pla0);
                atomicAdd(&g_p[rowA * 2 + 1], pla1);
                atomicAdd(&g_q[rowA * 2 + 0], pra0);
                atomicAdd(&g_q[rowA * 2 + 1], pra1);
            }
            if (rowB < N_NODES) {
                atomicAdd(&g_p[rowB * 2 + 0], plb0);
                atomicAdd(&g_p[rowB * 2 + 1], plb1);
                atomicAdd(&g_q[rowB * 2 + 0], prb0);
                atomicAdd(&g_q[rowB * 2 + 1], prb1);
            }
        }
    }
}

// ---------------- layer-2: aggregate p, add q, sigmoid, store ----------------
__global__ void k_aggout(const float* __restrict__ b2, float* __restrict__ out) {
    int i = blockIdx.x * blockDim.x + threadIdx.x;
    if (i >= N_NODES) return;
    int beg = g_rowptr[i], end = g_rowptr[i + 1];
    float a0 = 0.f, a1 = 0.f;
    const float2* p2 = (const float2*)g_p;
    for (int j = beg; j < end; j++) {
        float2 v = p2[g_nbr[j]];
        a0 += v.x; a1 += v.y;
    }
    float id = g_invdeg[i];
    float v0 = a0 * id + g_q[i * 2 + 0] + b2[0];
    float v1 = a1 * id + g_q[i * 2 + 1] + b2[1];
    out[i * 2 + 0] = 1.0f / (1.0f + __expf(-v0));
    out[i * 2 + 1] = 1.0f / (1.0f + __expf(-v1));
}

// ---------------- launch ------------------------------------------------------
extern "C" void kernel_launch(void* const* d_in, const int* in_sizes, int n_in,
                              void* d_out, int out_size) {
    const float* x   = (const float*)d_in[0];
    const int*   ei  = (const int*)d_in[1];
    const float* W1l = (const float*)d_in[2];
    const float* W1r = (const float*)d_in[3];
    const float* b1  = (const float*)d_in[4];
    const float* W2l = (const float*)d_in[5];
    const float* W2r = (const float*)d_in[6];
    const float* b2  = (const float*)d_in[7];

    float* out = (float*)d_out;
    float* emb = out + (size_t)N_NODES * 2;

    const int* src = ei;
    const int* dst = ei + N_EDGES;

    // prep: zero deg/p/q + convert W1 + convert x (one kernel)
    k_prep<<<(N_NODES * 32 + 255) / 256, 256>>>(W1l, W1r, x);

    // CSR build (multi-block scan)
    k_hist<<<(N_EDGES + 255) / 256, 256>>>(dst);
    k_scanA<<<SCAN_BLKS, 1024>>>();
    k_scanB<<<SCAN_BLKS, 1024>>>();
    k_scatter<<<(N_EDGES + 255) / 256, 256>>>(src, dst);

    // layer 1 aggregation (fp16 reads) + A conversion
    k_agg1c<<<(N_NODES + 7) / 8, 256>>>();

    // layer-1 GEMM (fp16 HMMA + ldmatrix) + fused layer-2 projections
    dim3 g1(M_TILES, 2);
    k_gemm1_mma<<<g1, 256>>>(b1, W2l, W2r, emb);

    // layer-2: aggregate 2-dim projections + output
    k_aggout<<<(N_NODES + 255) / 256, 256>>>(b2, out);
}